// round 1
// baseline (speedup 1.0000x reference)
#include <cuda_runtime.h>
#include <cuda_bf16.h>
#include <math.h>

#define N_ROWS 8192
#define DIM    128
#define NCLS   1000
#define EPS    1e-8f

// ---------------- device scratch (no allocations allowed) ----------------
__device__ float    g_xn[N_ROWS * DIM];          // normalized embeddings, 4 MB
__device__ float    g_p[N_ROWS];                 // exp((cos(x,proxy)-m)/T)
__device__ float    g_num[N_ROWS];
__device__ float    g_den[N_ROWS];
__device__ unsigned g_maskbits[NCLS * (N_ROWS / 32)];  // [class][jword], 1 MB

__device__ __forceinline__ float ex2f(float x) {
    float y;
    asm("ex2.approx.ftz.f32 %0, %1;" : "=f"(y) : "f"(x));
    return y;
}

// ---------------- kernel 1: normalize rows, proxy term, zero accum ----------------
__global__ void k_normalize(const float* __restrict__ x,
                            const float* __restrict__ proxy,
                            const float* __restrict__ tp,
                            const float* __restrict__ mp) {
    int gw   = (blockIdx.x * blockDim.x + threadIdx.x) >> 5;  // one warp per row
    int lane = threadIdx.x & 31;
    if (gw >= N_ROWS) return;

    const float4 v = *(const float4*)(x + gw * DIM + lane * 4);
    float ssx = v.x * v.x + v.y * v.y + v.z * v.z + v.w * v.w;

    const float4 pv = *(const float4*)(proxy + gw * DIM + lane * 4);
    float ssp = pv.x * pv.x + pv.y * pv.y + pv.z * pv.z + pv.w * pv.w;
    float dot = v.x * pv.x + v.y * pv.y + v.z * pv.z + v.w * pv.w;

    #pragma unroll
    for (int o = 16; o; o >>= 1) {
        ssx += __shfl_xor_sync(0xffffffffu, ssx, o);
        ssp += __shfl_xor_sync(0xffffffffu, ssp, o);
        dot += __shfl_xor_sync(0xffffffffu, dot, o);
    }
    float invx = 1.0f / fmaxf(sqrtf(ssx), EPS);
    float invp = 1.0f / fmaxf(sqrtf(ssp), EPS);

    float4 xn = make_float4(v.x * invx, v.y * invx, v.z * invx, v.w * invx);
    *(float4*)(g_xn + gw * DIM + lane * 4) = xn;

    if (lane == 0) {
        float T = tp[0], M = mp[0];
        float cosv = dot * invx * invp;
        g_p[gw]   = ex2f((cosv - M) * (1.4426950408889634f / T));
        g_num[gw] = 0.0f;
        g_den[gw] = 0.0f;
    }
}

// ---------------- kernel 2: pack negative_mask[j][c] into bits per class ----------------
// g_maskbits[c * 256 + jw] bit b  <=>  negative_mask[(jw*32+b)*NCLS + c] > 0.5
__global__ void k_pack(const float* __restrict__ nm) {
    __shared__ float s[32][33];
    int c0 = blockIdx.x * 32;
    int j0 = blockIdx.y * 32;
    int tx = threadIdx.x, ty = threadIdx.y;

    int c = c0 + tx;
    s[ty][tx] = (c < NCLS) ? nm[(j0 + ty) * NCLS + c] : 0.0f;
    __syncthreads();

    // warp ty handles class c0+ty; lane tx supplies bit for j0+tx
    float v = s[tx][ty];
    unsigned word = __ballot_sync(0xffffffffu, v > 0.5f);
    int cc = c0 + ty;
    if (tx == 0 && cc < NCLS)
        g_maskbits[cc * (N_ROWS / 32) + (j0 >> 5)] = word;
}

// ---------------- kernel 3: fused GEMM + exp + masked row sums ----------------
// Block: 256 threads, tile 64(i) x 64(j), K chunked 2x64.  grid (128, 2).
// smem: As[128][64] (k-major, XOR swizzled cols) + Bs[64][64]  = 48 KB exactly.
#define TM 64
#define TN 64
#define JSPLIT 2

__global__ void __launch_bounds__(256, 2)
k_main(const int* __restrict__ labels,
       const float* __restrict__ tp,
       const float* __restrict__ mp) {
    __shared__ float As[128 * TM];
    __shared__ float Bs[64 * TN];

    const int tid = threadIdx.x;
    const int tx = tid & 15;       // 4 j's per thread
    const int ty = tid >> 4;       // 4 i's per thread
    const int i0 = blockIdx.x * TM;
    const int jbase = blockIdx.y * (N_ROWS / JSPLIT);

    const float T = tp[0], M = mp[0];
    const float scale = 1.4426950408889634f / T;   // log2(e)/T
    const float nbias = -M * scale;

    // ---- load A tile (64 rows x 128 k), k-major with swizzle ----
    {
        int k4 = tid & 31;          // float4 index along k
        int rb = tid >> 5;          // 0..7
        #pragma unroll
        for (int p = 0; p < 8; ++p) {
            int r = p * 8 + rb;
            float4 v = *(const float4*)(g_xn + (i0 + r) * DIM + (k4 << 2));
            int kb = k4 << 2;
            const float* vp = (const float*)&v;
            #pragma unroll
            for (int q = 0; q < 4; ++q) {
                int k = kb + q;
                int sw = ((k >> 2) & 15) << 2;
                As[k * TM + (r ^ sw)] = vp[q];
            }
        }
    }

    int li[4];
    float den[4] = {0, 0, 0, 0}, num[4] = {0, 0, 0, 0};
    #pragma unroll
    for (int ii = 0; ii < 4; ++ii) li[ii] = labels[i0 + ty * 4 + ii];

    for (int jt = 0; jt < (N_ROWS / JSPLIT) / TN; ++jt) {
        const int j0 = jbase + jt * TN;
        float acc[4][4] = {};

        #pragma unroll
        for (int kc = 0; kc < 2; ++kc) {
            __syncthreads();
            // load B chunk: 64 j-rows x 64 k's, k-major with swizzle
            {
                int k4 = tid & 15;
                int rb = tid >> 4;
                #pragma unroll
                for (int p = 0; p < 4; ++p) {
                    int r = p * 16 + rb;
                    float4 v = *(const float4*)(g_xn + (j0 + r) * DIM + kc * 64 + (k4 << 2));
                    int kb = k4 << 2;
                    const float* vp = (const float*)&v;
                    #pragma unroll
                    for (int q = 0; q < 4; ++q) {
                        int k = kb + q;
                        int sw = ((k >> 2) & 15) << 2;
                        Bs[k * TN + (r ^ sw)] = vp[q];
                    }
                }
            }
            __syncthreads();

            #pragma unroll
            for (int k4 = 0; k4 < 16; ++k4) {
                int swA = (((kc * 16 + k4) & 15) << 2);
                int swB = ((k4 & 15) << 2);
                int aoff = (ty * 4) ^ swA;
                int boff = (tx * 4) ^ swB;
                #pragma unroll
                for (int q = 0; q < 4; ++q) {
                    int kf = (kc * 64 + k4 * 4 + q);
                    int kl = (k4 * 4 + q);
                    float4 a4 = *(const float4*)&As[kf * TM + aoff];
                    float4 b4 = *(const float4*)&Bs[kl * TN + boff];
                    const float* a = (const float*)&a4;
                    const float* b = (const float*)&b4;
                    #pragma unroll
                    for (int ii = 0; ii < 4; ++ii)
                        #pragma unroll
                        for (int jj = 0; jj < 4; ++jj)
                            acc[ii][jj] = fmaf(a[ii], b[jj], acc[ii][jj]);
                }
            }
        }

        // ---- epilogue: exp, diag removal, masked sums ----
        const int wbase = (j0 >> 5) + (tx >> 3);
        #pragma unroll
        for (int ii = 0; ii < 4; ++ii) {
            unsigned w = g_maskbits[li[ii] * (N_ROWS / 32) + wbase];
            int ig = i0 + ty * 4 + ii;
            #pragma unroll
            for (int jj = 0; jj < 4; ++jj) {
                int jl = tx * 4 + jj;
                int jg = j0 + jl;
                float e = ex2f(fmaf(acc[ii][jj], scale, nbias));
                e = (jg == ig) ? 0.0f : e;
                den[ii] += e;
                num[ii] += ((w >> (jl & 31)) & 1u) ? e : 0.0f;
            }
        }
    }

    // reduce across the 16 tx lanes (within half-warps), then atomics
    #pragma unroll
    for (int ii = 0; ii < 4; ++ii) {
        #pragma unroll
        for (int m = 8; m; m >>= 1) {
            den[ii] += __shfl_xor_sync(0xffffffffu, den[ii], m);
            num[ii] += __shfl_xor_sync(0xffffffffu, num[ii], m);
        }
    }
    if (tx == 0) {
        #pragma unroll
        for (int ii = 0; ii < 4; ++ii) {
            int ig = i0 + ty * 4 + ii;
            atomicAdd(&g_den[ig], den[ii]);
            atomicAdd(&g_num[ig], num[ii]);
        }
    }
}

// ---------------- kernel 4: final loss reduction ----------------
__global__ void k_final(float* __restrict__ out, const float* __restrict__ tp) {
    __shared__ float s[256];
    float T = tp[0];
    float sum = 0.0f;
    for (int r = threadIdx.x; r < N_ROWS; r += 256) {
        float p = g_p[r];
        sum += -logf(T * (p + g_num[r]) / (p + g_den[r]));
    }
    s[threadIdx.x] = sum;
    __syncthreads();
    #pragma unroll
    for (int o = 128; o; o >>= 1) {
        if (threadIdx.x < o) s[threadIdx.x] += s[threadIdx.x + o];
        __syncthreads();
    }
    if (threadIdx.x == 0) out[0] = s[0] / (float)N_ROWS;
}

// ---------------- launch ----------------
extern "C" void kernel_launch(void* const* d_in, const int* in_sizes, int n_in,
                              void* d_out, int out_size) {
    const float* inst  = (const float*)d_in[0];
    const float* proxy = (const float*)d_in[1];
    const float* nmask = (const float*)d_in[2];
    const int*   lab   = (const int*)d_in[3];
    const float* temp  = (const float*)d_in[4];
    const float* marg  = (const float*)d_in[5];
    float* out = (float*)d_out;

    k_normalize<<<(N_ROWS * 32) / 256, 256>>>(inst, proxy, temp, marg);
    k_pack<<<dim3((NCLS + 31) / 32, N_ROWS / 32), dim3(32, 32)>>>(nmask);
    k_main<<<dim3(N_ROWS / TM, JSPLIT), 256>>>(lab, temp, marg);
    k_final<<<1, 256>>>(out, temp);
}

// round 3
// speedup vs baseline: 2.9394x; 2.9394x over previous
#include <cuda_runtime.h>
#include <cuda_bf16.h>
#include <math.h>
#include <cstdint>

#define N_ROWS 8192
#define DIM    128
#define NCLS   1000
#define EPS    1e-8f

#define TM 128
#define TN 128
#define JSPLIT 2
#define NT_TILES ((N_ROWS / JSPLIT) / TN)   // 32

// ---------------- device scratch ----------------
__device__ __align__(16) __nv_bfloat16 g_xh[N_ROWS * DIM];   // hi part, 2 MB
__device__ __align__(16) __nv_bfloat16 g_xl[N_ROWS * DIM];   // lo part, 2 MB
__device__ float    g_p[N_ROWS];
__device__ float    g_num[N_ROWS];
__device__ float    g_den[N_ROWS];
__device__ unsigned g_maskbits[NCLS * (N_ROWS / 32)];        // [class][jword]

// ---------------- helpers ----------------
__device__ __forceinline__ float ex2f(float x) {
    float y; asm("ex2.approx.ftz.f32 %0, %1;" : "=f"(y) : "f"(x)); return y;
}
__device__ __forceinline__ uint32_t smem_u32(const void* p) {
    uint32_t a;
    asm("{ .reg .u64 t; cvta.to.shared.u64 t, %1; cvt.u32.u64 %0, t; }" : "=r"(a) : "l"(p));
    return a;
}
__device__ __forceinline__ void cp16(uint32_t dst, const void* src) {
    asm volatile("cp.async.ca.shared.global [%0], [%1], 16;" :: "r"(dst), "l"(src));
}
#define CP_COMMIT() asm volatile("cp.async.commit_group;" ::: "memory")
#define CP_WAIT(n)  asm volatile("cp.async.wait_group %0;" :: "n"(n) : "memory")

#define LDSM_X4(r0,r1,r2,r3,a) \
    asm volatile("ldmatrix.sync.aligned.m8n8.x4.shared.b16 {%0,%1,%2,%3}, [%4];" \
        : "=r"(r0),"=r"(r1),"=r"(r2),"=r"(r3) : "r"(a))
#define LDSM_X2(r0,r1,a) \
    asm volatile("ldmatrix.sync.aligned.m8n8.x2.shared.b16 {%0,%1}, [%2];" \
        : "=r"(r0),"=r"(r1) : "r"(a))

__device__ __forceinline__ void mma16816(float* d, const uint32_t* a, const uint32_t* b) {
    asm volatile("mma.sync.aligned.m16n8k16.row.col.f32.bf16.bf16.f32 "
        "{%0,%1,%2,%3}, {%4,%5,%6,%7}, {%8,%9}, {%0,%1,%2,%3};"
        : "+f"(d[0]), "+f"(d[1]), "+f"(d[2]), "+f"(d[3])
        : "r"(a[0]), "r"(a[1]), "r"(a[2]), "r"(a[3]), "r"(b[0]), "r"(b[1]));
}

// smem tile layout: 128 rows x 256B, 16B chunks XOR-swizzled by row
__device__ __forceinline__ uint32_t toff(int row, int ch) {
    return (uint32_t)(row * 256 + ((ch ^ (row & 7)) << 4));
}

// smem offsets (bytes): AH 0, AL 32K, B buffers at 64K + s*64K (hi), +32K (lo)
#define OFF_AL  32768
#define OFF_B   65536
#define SMEM_TOTAL (65536 + 2 * 65536)   // 192 KB

// ---------------- kernel 1: normalize + split + proxy term ----------------
__global__ void k_normalize(const float* __restrict__ x,
                            const float* __restrict__ proxy,
                            const float* __restrict__ tp,
                            const float* __restrict__ mp) {
    int gw   = (blockIdx.x * blockDim.x + threadIdx.x) >> 5;
    int lane = threadIdx.x & 31;
    if (gw >= N_ROWS) return;

    const float4 v  = *(const float4*)(x + gw * DIM + lane * 4);
    float ssx = v.x * v.x + v.y * v.y + v.z * v.z + v.w * v.w;
    const float4 pv = *(const float4*)(proxy + gw * DIM + lane * 4);
    float ssp = pv.x * pv.x + pv.y * pv.y + pv.z * pv.z + pv.w * pv.w;
    float dot = v.x * pv.x + v.y * pv.y + v.z * pv.z + v.w * pv.w;

    #pragma unroll
    for (int o = 16; o; o >>= 1) {
        ssx += __shfl_xor_sync(0xffffffffu, ssx, o);
        ssp += __shfl_xor_sync(0xffffffffu, ssp, o);
        dot += __shfl_xor_sync(0xffffffffu, dot, o);
    }
    float invx = 1.0f / fmaxf(sqrtf(ssx), EPS);
    float invp = 1.0f / fmaxf(sqrtf(ssp), EPS);

    const float xs[4] = {v.x * invx, v.y * invx, v.z * invx, v.w * invx};
    #pragma unroll
    for (int q = 0; q < 4; ++q) {
        __nv_bfloat16 hb = __float2bfloat16(xs[q]);
        g_xh[gw * DIM + lane * 4 + q] = hb;
        g_xl[gw * DIM + lane * 4 + q] = __float2bfloat16(xs[q] - __bfloat162float(hb));
    }

    if (lane == 0) {
        float T = tp[0], M = mp[0];
        float cosv = dot * invx * invp;
        g_p[gw]   = ex2f((cosv - M) * (1.4426950408889634f / T));
        g_num[gw] = 0.0f;
        g_den[gw] = 0.0f;
    }
}

// ---------------- kernel 2: pack mask bits per class ----------------
__global__ void k_pack(const float* __restrict__ nm) {
    __shared__ float s[32][33];
    int c0 = blockIdx.x * 32;
    int j0 = blockIdx.y * 32;
    int tx = threadIdx.x, ty = threadIdx.y;
    int c = c0 + tx;
    s[ty][tx] = (c < NCLS) ? nm[(j0 + ty) * NCLS + c] : 0.0f;
    __syncthreads();
    float v = s[tx][ty];
    unsigned word = __ballot_sync(0xffffffffu, v > 0.5f);
    int cc = c0 + ty;
    if (tx == 0 && cc < NCLS)
        g_maskbits[cc * (N_ROWS / 32) + (j0 >> 5)] = word;
}

// ---------------- kernel 3: mma.sync fused GEMM + exp + masked sums ----------------
__device__ __forceinline__ void prefetch_tile(uint32_t dstbase, int row0, int tid) {
    // 4096 16B chunks: hi matrix then lo matrix, 16 per thread
    #pragma unroll
    for (int it = 0; it < 16; ++it) {
        int c = tid + it * 256;
        int mat = c >> 11;
        int rem = c & 2047;
        int row = rem >> 4, ch = rem & 15;
        const void* src = (const void*)((mat ? g_xl : g_xh) + (row0 + row) * DIM + ch * 8);
        cp16(dstbase + (uint32_t)(mat * 32768) + toff(row, ch), src);
    }
}

__global__ void __launch_bounds__(256, 1)
k_main(const int* __restrict__ labels,
       const float* __restrict__ tp,
       const float* __restrict__ mp) {
    extern __shared__ char smem[];
    const uint32_t sb = smem_u32(smem);
    const int tid  = threadIdx.x;
    const int lane = tid & 31;
    const int wid  = tid >> 5;
    const int wm = wid >> 2;     // 0..1 : i block of 64
    const int wn = wid & 3;      // 0..3 : j block of 32
    const int i0 = blockIdx.x * TM;
    const int jbase = blockIdx.y * (N_ROWS / JSPLIT);

    const float T = tp[0], M = mp[0];
    const float scale = 1.4426950408889634f / T;
    const float nbias = -M * scale;

    // A/B ldmatrix lane addressing components
    const int arow_l = lane & 15;          // local row within 16
    const int akc    = lane >> 4;          // k-chunk select (0/1)
    const int brow_l = lane & 7;
    const int bkc    = (lane >> 3) & 1;

    // my 8 rows (mt 0..3 x half 0..1) and their labels
    int   li8[8];
    float dacc[8], nacc[8];
    #pragma unroll
    for (int r = 0; r < 8; ++r) {
        int ig = i0 + wm * 64 + (r >> 1) * 16 + (lane >> 2) + (r & 1) * 8;
        li8[r] = labels[ig];
        dacc[r] = 0.0f; nacc[r] = 0.0f;
    }

    // prime pipeline: A (resident) + B tile0 in group0, B tile1 in group1
    prefetch_tile(sb, i0, tid);                    // A hi/lo at offset 0
    prefetch_tile(sb + OFF_B, jbase, tid);         // B buf 0
    CP_COMMIT();
    prefetch_tile(sb + OFF_B + 65536, jbase + TN, tid);  // B buf 1
    CP_COMMIT();

    for (int t = 0; t < NT_TILES; ++t) {
        if (t >= NT_TILES - 2) { CP_WAIT(0); } else { CP_WAIT(1); }
        __syncthreads();

        const int j0 = jbase + t * TN;
        const uint32_t Bh = sb + OFF_B + (uint32_t)((t & 1) * 65536);
        const uint32_t Bl = Bh + 32768;
        const uint32_t Ah = sb;
        const uint32_t Al = sb + OFF_AL;

        float acc[4][4][4];
        #pragma unroll
        for (int a = 0; a < 4; ++a)
            #pragma unroll
            for (int b = 0; b < 4; ++b)
                #pragma unroll
                for (int c = 0; c < 4; ++c) acc[a][b][c] = 0.0f;

        #pragma unroll
        for (int kk = 0; kk < 8; ++kk) {
            uint32_t ah[4][4], al[4][4], bh[4][2], bl[4][2];
            #pragma unroll
            for (int mt = 0; mt < 4; ++mt) {
                int row = wm * 64 + mt * 16 + arow_l;
                uint32_t off = toff(row, kk * 2 + akc);
                LDSM_X4(ah[mt][0], ah[mt][1], ah[mt][2], ah[mt][3], Ah + off);
                LDSM_X4(al[mt][0], al[mt][1], al[mt][2], al[mt][3], Al + off);
            }
            #pragma unroll
            for (int nt = 0; nt < 4; ++nt) {
                int row = wn * 32 + nt * 8 + brow_l;
                uint32_t off = toff(row, kk * 2 + bkc);
                LDSM_X2(bh[nt][0], bh[nt][1], Bh + off);
                LDSM_X2(bl[nt][0], bl[nt][1], Bl + off);
            }
            #pragma unroll
            for (int mt = 0; mt < 4; ++mt)
                #pragma unroll
                for (int nt = 0; nt < 4; ++nt) {
                    mma16816(acc[mt][nt], ah[mt], bh[nt]);   // hh
                    mma16816(acc[mt][nt], ah[mt], bl[nt]);   // hl
                    mma16816(acc[mt][nt], al[mt], bh[nt]);   // lh
                }
        }

        __syncthreads();
        if (t + 2 < NT_TILES) {
            prefetch_tile(sb + OFF_B + (uint32_t)((t & 1) * 65536), jbase + (t + 2) * TN, tid);
            CP_COMMIT();
        }

        // epilogue on register accumulators
        const int wword = (j0 >> 5) + wn;
        #pragma unroll
        for (int mt = 0; mt < 4; ++mt) {
            #pragma unroll
            for (int h = 0; h < 2; ++h) {
                const int r = mt * 2 + h;
                const unsigned w = g_maskbits[li8[r] * (N_ROWS / 32) + wword];
                const int ig = i0 + wm * 64 + mt * 16 + (lane >> 2) + h * 8;
                float de = 0.0f, nu = 0.0f;
                #pragma unroll
                for (int nt = 0; nt < 4; ++nt) {
                    #pragma unroll
                    for (int e = 0; e < 2; ++e) {
                        int col = wn * 32 + nt * 8 + (lane & 3) * 2 + e;
                        float ex = ex2f(fmaf(acc[mt][nt][h * 2 + e], scale, nbias));
                        ex = (j0 + col == ig) ? 0.0f : ex;
                        de += ex;
                        nu += ((w >> (col & 31)) & 1u) ? ex : 0.0f;
                    }
                }
                dacc[r] += de;
                nacc[r] += nu;
            }
        }
    }

    // quad reduce (lanes sharing the same row) and atomics
    #pragma unroll
    for (int r = 0; r < 8; ++r) {
        #pragma unroll
        for (int m = 1; m <= 2; m <<= 1) {
            dacc[r] += __shfl_xor_sync(0xffffffffu, dacc[r], m);
            nacc[r] += __shfl_xor_sync(0xffffffffu, nacc[r], m);
        }
    }
    if ((lane & 3) == 0) {
        #pragma unroll
        for (int r = 0; r < 8; ++r) {
            int ig = i0 + wm * 64 + (r >> 1) * 16 + (lane >> 2) + (r & 1) * 8;
            atomicAdd(&g_den[ig], dacc[r]);
            atomicAdd(&g_num[ig], nacc[r]);
        }
    }
}

// ---------------- kernel 4: final loss reduction ----------------
__global__ void k_final(float* __restrict__ out, const float* __restrict__ tp) {
    __shared__ float s[1024];
    float T = tp[0];
    float sum = 0.0f;
    for (int r = threadIdx.x; r < N_ROWS; r += 1024) {
        float p = g_p[r];
        sum += -__logf(T * (p + g_num[r]) / (p + g_den[r]));
    }
    s[threadIdx.x] = sum;
    __syncthreads();
    #pragma unroll
    for (int o = 512; o; o >>= 1) {
        if (threadIdx.x < o) s[threadIdx.x] += s[threadIdx.x + o];
        __syncthreads();
    }
    if (threadIdx.x == 0) out[0] = s[0] / (float)N_ROWS;
}

// ---------------- launch ----------------
extern "C" void kernel_launch(void* const* d_in, const int* in_sizes, int n_in,
                              void* d_out, int out_size) {
    const float* inst  = (const float*)d_in[0];
    const float* proxy = (const float*)d_in[1];
    const float* nmask = (const float*)d_in[2];
    const int*   lab   = (const int*)d_in[3];
    const float* temp  = (const float*)d_in[4];
    const float* marg  = (const float*)d_in[5];
    float* out = (float*)d_out;

    cudaFuncSetAttribute(k_main, cudaFuncAttributeMaxDynamicSharedMemorySize, SMEM_TOTAL);

    k_normalize<<<(N_ROWS * 32) / 256, 256>>>(inst, proxy, temp, marg);
    k_pack<<<dim3((NCLS + 31) / 32, N_ROWS / 32), dim3(32, 32)>>>(nmask);
    k_main<<<dim3(N_ROWS / TM, JSPLIT), 256, SMEM_TOTAL>>>(lab, temp, marg);
    k_final<<<1, 1024>>>(out, temp);
}

// round 4
// speedup vs baseline: 3.1344x; 1.0663x over previous
#include <cuda_runtime.h>
#include <cuda_bf16.h>
#include <math.h>
#include <cstdint>

#define N_ROWS 8192
#define DIM    128
#define NCLS   1000
#define EPS    1e-8f

#define TM 128
#define TN 128
#define JSPLIT 2
#define NT_TILES ((N_ROWS / JSPLIT) / TN)   // 32

// ---------------- device scratch ----------------
__device__ __align__(16) __nv_bfloat16 g_xh[N_ROWS * DIM];   // hi part, 2 MB
__device__ __align__(16) __nv_bfloat16 g_xl[N_ROWS * DIM];   // lo part, 2 MB
__device__ float    g_p[N_ROWS];
__device__ float    g_num[N_ROWS];
__device__ float    g_den[N_ROWS];
__device__ unsigned g_maskbits[NCLS * (N_ROWS / 32)];        // [class][jword]

// ---------------- helpers ----------------
__device__ __forceinline__ float ex2f(float x) {
    float y; asm("ex2.approx.ftz.f32 %0, %1;" : "=f"(y) : "f"(x)); return y;
}
__device__ __forceinline__ uint32_t smem_u32(const void* p) {
    uint32_t a;
    asm("{ .reg .u64 t; cvta.to.shared.u64 t, %1; cvt.u32.u64 %0, t; }" : "=r"(a) : "l"(p));
    return a;
}
__device__ __forceinline__ void cp16(uint32_t dst, const void* src) {
    asm volatile("cp.async.cg.shared.global [%0], [%1], 16;" :: "r"(dst), "l"(src));
}
#define CP_COMMIT() asm volatile("cp.async.commit_group;" ::: "memory")
#define CP_WAIT(n)  asm volatile("cp.async.wait_group %0;" :: "n"(n) : "memory")

#define LDSM_X4(r0,r1,r2,r3,a) \
    asm volatile("ldmatrix.sync.aligned.m8n8.x4.shared.b16 {%0,%1,%2,%3}, [%4];" \
        : "=r"(r0),"=r"(r1),"=r"(r2),"=r"(r3) : "r"(a))

__device__ __forceinline__ void mma16816(float* d, const uint32_t* a, const uint32_t* b) {
    asm volatile("mma.sync.aligned.m16n8k16.row.col.f32.bf16.bf16.f32 "
        "{%0,%1,%2,%3}, {%4,%5,%6,%7}, {%8,%9}, {%0,%1,%2,%3};"
        : "+f"(d[0]), "+f"(d[1]), "+f"(d[2]), "+f"(d[3])
        : "r"(a[0]), "r"(a[1]), "r"(a[2]), "r"(a[3]), "r"(b[0]), "r"(b[1]));
}

// smem tile layout: 128 rows x 256B, 16B chunks XOR-swizzled by row
__device__ __forceinline__ uint32_t toff(int row, int ch) {
    return (uint32_t)(row * 256 + ((ch ^ (row & 7)) << 4));
}

#define OFF_AL  32768
#define OFF_B   65536
#define SMEM_TOTAL (65536 + 2 * 65536)   // 192 KB

// ---------------- kernel 1: normalize + split + proxy term ----------------
__global__ void k_normalize(const float* __restrict__ x,
                            const float* __restrict__ proxy,
                            const float* __restrict__ tp,
                            const float* __restrict__ mp) {
    int gw   = (blockIdx.x * blockDim.x + threadIdx.x) >> 5;
    int lane = threadIdx.x & 31;
    if (gw >= N_ROWS) return;

    const float4 v  = *(const float4*)(x + gw * DIM + lane * 4);
    float ssx = v.x * v.x + v.y * v.y + v.z * v.z + v.w * v.w;
    const float4 pv = *(const float4*)(proxy + gw * DIM + lane * 4);
    float ssp = pv.x * pv.x + pv.y * pv.y + pv.z * pv.z + pv.w * pv.w;
    float dot = v.x * pv.x + v.y * pv.y + v.z * pv.z + v.w * pv.w;

    #pragma unroll
    for (int o = 16; o; o >>= 1) {
        ssx += __shfl_xor_sync(0xffffffffu, ssx, o);
        ssp += __shfl_xor_sync(0xffffffffu, ssp, o);
        dot += __shfl_xor_sync(0xffffffffu, dot, o);
    }
    float invx = 1.0f / fmaxf(sqrtf(ssx), EPS);
    float invp = 1.0f / fmaxf(sqrtf(ssp), EPS);

    const float xs[4] = {v.x * invx, v.y * invx, v.z * invx, v.w * invx};
    #pragma unroll
    for (int q = 0; q < 4; ++q) {
        __nv_bfloat16 hb = __float2bfloat16(xs[q]);
        g_xh[gw * DIM + lane * 4 + q] = hb;
        g_xl[gw * DIM + lane * 4 + q] = __float2bfloat16(xs[q] - __bfloat162float(hb));
    }

    if (lane == 0) {
        float T = tp[0], M = mp[0];
        float cosv = dot * invx * invp;
        g_p[gw]   = ex2f((cosv - M) * (1.4426950408889634f / T));
        g_num[gw] = 0.0f;
        g_den[gw] = 0.0f;
    }
}

// ---------------- kernel 2: pack mask bits per class ----------------
__global__ void k_pack(const float* __restrict__ nm) {
    __shared__ float s[32][33];
    int c0 = blockIdx.x * 32;
    int j0 = blockIdx.y * 32;
    int tx = threadIdx.x, ty = threadIdx.y;
    int c = c0 + tx;
    s[ty][tx] = (c < NCLS) ? nm[(j0 + ty) * NCLS + c] : 0.0f;
    __syncthreads();
    float v = s[tx][ty];
    unsigned word = __ballot_sync(0xffffffffu, v > 0.5f);
    int cc = c0 + ty;
    if (tx == 0 && cc < NCLS)
        g_maskbits[cc * (N_ROWS / 32) + (j0 >> 5)] = word;
}

// ---------------- kernel 3: mma.sync fused GEMM + exp + masked sums ----------------
__device__ __forceinline__ void prefetch_tile(uint32_t dstbase, int row0, int tid) {
    // 4096 16B chunks: hi matrix then lo matrix, 8 per thread (512 threads)
    #pragma unroll
    for (int it = 0; it < 8; ++it) {
        int c = tid + it * 512;
        int mat = c >> 11;
        int rem = c & 2047;
        int row = rem >> 4, ch = rem & 15;
        const void* src = (const void*)((mat ? g_xl : g_xh) + (row0 + row) * DIM + ch * 8);
        cp16(dstbase + (uint32_t)(mat * 32768) + toff(row, ch), src);
    }
}

__global__ void __launch_bounds__(512, 1)
k_main(const int* __restrict__ labels,
       const float* __restrict__ tp,
       const float* __restrict__ mp) {
    extern __shared__ char smem[];
    const uint32_t sb = smem_u32(smem);
    const int tid  = threadIdx.x;
    const int lane = tid & 31;
    const int wid  = tid >> 5;
    const int wm = wid >> 2;     // 0..3 : i block of 32
    const int wn = wid & 3;      // 0..3 : j block of 32
    const int i0 = blockIdx.x * TM;
    const int jbase = blockIdx.y * (N_ROWS / JSPLIT);

    const float T = tp[0], M = mp[0];
    const float scale = 1.4426950408889634f / T;
    const float nbias = -M * scale;

    // ldmatrix lane addressing
    const int arow_l = lane & 15;          // A: row within 16-row group
    const int akc    = lane >> 4;          // A: k-chunk select
    const int bnt_h  = (lane >> 4) & 1;    // B: nt within pair
    const int bkc    = (lane >> 3) & 1;    // B: k-chunk select
    const int brow_l = lane & 7;

    // my 4 rows (mt 0..1 x half 0..1)
    int   li4[4];
    float dacc[4], nacc[4];
    #pragma unroll
    for (int r = 0; r < 4; ++r) {
        int ig = i0 + wm * 32 + (r >> 1) * 16 + (lane >> 2) + (r & 1) * 8;
        li4[r] = labels[ig];
        dacc[r] = 0.0f; nacc[r] = 0.0f;
    }

    prefetch_tile(sb, i0, tid);                          // A hi/lo resident
    prefetch_tile(sb + OFF_B, jbase, tid);               // B buf 0
    CP_COMMIT();
    prefetch_tile(sb + OFF_B + 65536, jbase + TN, tid);  // B buf 1
    CP_COMMIT();

    for (int t = 0; t < NT_TILES; ++t) {
        if (t >= NT_TILES - 2) { CP_WAIT(0); } else { CP_WAIT(1); }
        __syncthreads();

        const int j0 = jbase + t * TN;
        const uint32_t Bh = sb + OFF_B + (uint32_t)((t & 1) * 65536);
        const uint32_t Bl = Bh + 32768;
        const uint32_t Ah = sb;
        const uint32_t Al = sb + OFF_AL;

        float acc[2][4][4];
        #pragma unroll
        for (int a = 0; a < 2; ++a)
            #pragma unroll
            for (int b = 0; b < 4; ++b)
                #pragma unroll
                for (int c = 0; c < 4; ++c) acc[a][b][c] = 0.0f;

        #pragma unroll
        for (int kk = 0; kk < 8; ++kk) {
            uint32_t ah[2][4], al[2][4], bh[4][2], bl[4][2];
            #pragma unroll
            for (int mt = 0; mt < 2; ++mt) {
                int row = wm * 32 + mt * 16 + arow_l;
                uint32_t off = toff(row, kk * 2 + akc);
                LDSM_X4(ah[mt][0], ah[mt][1], ah[mt][2], ah[mt][3], Ah + off);
                LDSM_X4(al[mt][0], al[mt][1], al[mt][2], al[mt][3], Al + off);
            }
            // B: one x4 covers nt pair (2*ntp, 2*ntp+1) x both k-chunks
            #pragma unroll
            for (int ntp = 0; ntp < 2; ++ntp) {
                int row = wn * 32 + (ntp * 2 + bnt_h) * 8 + brow_l;
                uint32_t off = toff(row, kk * 2 + bkc);
                LDSM_X4(bh[ntp * 2][0], bh[ntp * 2][1],
                        bh[ntp * 2 + 1][0], bh[ntp * 2 + 1][1], Bh + off);
                LDSM_X4(bl[ntp * 2][0], bl[ntp * 2][1],
                        bl[ntp * 2 + 1][0], bl[ntp * 2 + 1][1], Bl + off);
            }
            #pragma unroll
            for (int mt = 0; mt < 2; ++mt)
                #pragma unroll
                for (int nt = 0; nt < 4; ++nt) {
                    mma16816(acc[mt][nt], ah[mt], bh[nt]);   // hh
                    mma16816(acc[mt][nt], ah[mt], bl[nt]);   // hl
                    mma16816(acc[mt][nt], al[mt], bh[nt]);   // lh
                }
        }

        __syncthreads();
        if (t + 2 < NT_TILES) {
            prefetch_tile(sb + OFF_B + (uint32_t)((t & 1) * 65536), jbase + (t + 2) * TN, tid);
            CP_COMMIT();
        }

        // epilogue on register accumulators
        const int wword = (j0 >> 5) + wn;
        #pragma unroll
        for (int mt = 0; mt < 2; ++mt) {
            #pragma unroll
            for (int h = 0; h < 2; ++h) {
                const int r = mt * 2 + h;
                const unsigned w = g_maskbits[li4[r] * (N_ROWS / 32) + wword];
                const int ig = i0 + wm * 32 + mt * 16 + (lane >> 2) + h * 8;
                float de = 0.0f, nu = 0.0f;
                #pragma unroll
                for (int nt = 0; nt < 4; ++nt) {
                    #pragma unroll
                    for (int e = 0; e < 2; ++e) {
                        int col = wn * 32 + nt * 8 + (lane & 3) * 2 + e;
                        float ex = ex2f(fmaf(acc[mt][nt][h * 2 + e], scale, nbias));
                        ex = (j0 + col == ig) ? 0.0f : ex;
                        de += ex;
                        nu += ((w >> (col & 31)) & 1u) ? ex : 0.0f;
                    }
                }
                dacc[r] += de;
                nacc[r] += nu;
            }
        }
    }

    // quad reduce (lanes sharing the same row) and atomics
    #pragma unroll
    for (int r = 0; r < 4; ++r) {
        #pragma unroll
        for (int m = 1; m <= 2; m <<= 1) {
            dacc[r] += __shfl_xor_sync(0xffffffffu, dacc[r], m);
            nacc[r] += __shfl_xor_sync(0xffffffffu, nacc[r], m);
        }
    }
    if ((lane & 3) == 0) {
        #pragma unroll
        for (int r = 0; r < 4; ++r) {
            int ig = i0 + wm * 32 + (r >> 1) * 16 + (lane >> 2) + (r & 1) * 8;
            atomicAdd(&g_den[ig], dacc[r]);
            atomicAdd(&g_num[ig], nacc[r]);
        }
    }
}

// ---------------- kernel 4: final loss reduction (8 blocks, atomic) ----------------
__global__ void k_final(float* __restrict__ out, const float* __restrict__ tp) {
    __shared__ float s[1024];
    float T = tp[0];
    float sum = 0.0f;
    int base = blockIdx.x * 1024;
    for (int r = base + threadIdx.x; r < N_ROWS; r += 8192) {
        float p = g_p[r];
        sum += -__logf(T * (p + g_num[r]) / (p + g_den[r]));
    }
    s[threadIdx.x] = sum;
    __syncthreads();
    #pragma unroll
    for (int o = 512; o >= 32; o >>= 1) {
        if (threadIdx.x < o) s[threadIdx.x] += s[threadIdx.x + o];
        __syncthreads();
    }
    if (threadIdx.x < 32) {
        float v = s[threadIdx.x];
        #pragma unroll
        for (int m = 16; m; m >>= 1) v += __shfl_xor_sync(0xffffffffu, v, m);
        if (threadIdx.x == 0) atomicAdd(out, v / (float)N_ROWS);
    }
}

// ---------------- launch ----------------
extern "C" void kernel_launch(void* const* d_in, const int* in_sizes, int n_in,
                              void* d_out, int out_size) {
    const float* inst  = (const float*)d_in[0];
    const float* proxy = (const float*)d_in[1];
    const float* nmask = (const float*)d_in[2];
    const int*   lab   = (const int*)d_in[3];
    const float* temp  = (const float*)d_in[4];
    const float* marg  = (const float*)d_in[5];
    float* out = (float*)d_out;

    cudaFuncSetAttribute(k_main, cudaFuncAttributeMaxDynamicSharedMemorySize, SMEM_TOTAL);

    cudaMemsetAsync(out, 0, sizeof(float));
    k_normalize<<<(N_ROWS * 32) / 256, 256>>>(inst, proxy, temp, marg);
    k_pack<<<dim3((NCLS + 31) / 32, N_ROWS / 32), dim3(32, 32)>>>(nmask);
    k_main<<<dim3(N_ROWS / TM, JSPLIT), 512, SMEM_TOTAL>>>(lab, temp, marg);
    k_final<<<8, 1024>>>(out, temp);
}

// round 5
// speedup vs baseline: 5.6632x; 1.8068x over previous
#include <cuda_runtime.h>
#include <cuda_fp16.h>
#include <math.h>
#include <cstdint>

#define N_ROWS 8192
#define DIM    128
#define NCLS   1000
#define EPS    1e-8f

#define TM 128
#define TN 128
#define JSPLIT 4
#define NT_TILES ((N_ROWS / JSPLIT) / TN)   // 16

// ---------------- device scratch ----------------
__device__ __align__(16) __half g_xh[N_ROWS * DIM];          // fp16 normalized, 2 MB
__device__ float    g_p[N_ROWS];
__device__ float    g_num[N_ROWS];
__device__ float    g_den[N_ROWS];
__device__ unsigned g_maskbits[NCLS * (N_ROWS / 32)];        // [class][jword]

// ---------------- helpers ----------------
__device__ __forceinline__ float ex2f(float x) {
    float y; asm("ex2.approx.ftz.f32 %0, %1;" : "=f"(y) : "f"(x)); return y;
}
__device__ __forceinline__ uint32_t smem_u32(const void* p) {
    uint32_t a;
    asm("{ .reg .u64 t; cvta.to.shared.u64 t, %1; cvt.u32.u64 %0, t; }" : "=r"(a) : "l"(p));
    return a;
}
__device__ __forceinline__ void cp16(uint32_t dst, const void* src) {
    asm volatile("cp.async.cg.shared.global [%0], [%1], 16;" :: "r"(dst), "l"(src));
}
#define CP_COMMIT() asm volatile("cp.async.commit_group;" ::: "memory")
#define CP_WAIT(n)  asm volatile("cp.async.wait_group %0;" :: "n"(n) : "memory")

#define LDSM_X4(r0,r1,r2,r3,a) \
    asm volatile("ldmatrix.sync.aligned.m8n8.x4.shared.b16 {%0,%1,%2,%3}, [%4];" \
        : "=r"(r0),"=r"(r1),"=r"(r2),"=r"(r3) : "r"(a))

__device__ __forceinline__ void mma16816(float* d, const uint32_t* a, const uint32_t* b) {
    asm volatile("mma.sync.aligned.m16n8k16.row.col.f32.f16.f16.f32 "
        "{%0,%1,%2,%3}, {%4,%5,%6,%7}, {%8,%9}, {%0,%1,%2,%3};"
        : "+f"(d[0]), "+f"(d[1]), "+f"(d[2]), "+f"(d[3])
        : "r"(a[0]), "r"(a[1]), "r"(a[2]), "r"(a[3]), "r"(b[0]), "r"(b[1]));
}

// smem tile layout: 128 rows x 256B, 16B chunks XOR-swizzled by row
__device__ __forceinline__ uint32_t toff(int row, int ch) {
    return (uint32_t)(row * 256 + ((ch ^ (row & 7)) << 4));
}

#define OFF_B   32768
#define SMEM_TOTAL (32768 + 2 * 32768)   // 96 KB

// ---------------- kernel 1: normalize + fp16 cast + proxy term ----------------
__global__ void k_normalize(const float* __restrict__ x,
                            const float* __restrict__ proxy,
                            const float* __restrict__ tp,
                            const float* __restrict__ mp) {
    int gw   = (blockIdx.x * blockDim.x + threadIdx.x) >> 5;
    int lane = threadIdx.x & 31;
    if (gw >= N_ROWS) return;

    const float4 v  = *(const float4*)(x + gw * DIM + lane * 4);
    float ssx = v.x * v.x + v.y * v.y + v.z * v.z + v.w * v.w;
    const float4 pv = *(const float4*)(proxy + gw * DIM + lane * 4);
    float ssp = pv.x * pv.x + pv.y * pv.y + pv.z * pv.z + pv.w * pv.w;
    float dot = v.x * pv.x + v.y * pv.y + v.z * pv.z + v.w * pv.w;

    #pragma unroll
    for (int o = 16; o; o >>= 1) {
        ssx += __shfl_xor_sync(0xffffffffu, ssx, o);
        ssp += __shfl_xor_sync(0xffffffffu, ssp, o);
        dot += __shfl_xor_sync(0xffffffffu, dot, o);
    }
    float invx = 1.0f / fmaxf(sqrtf(ssx), EPS);
    float invp = 1.0f / fmaxf(sqrtf(ssp), EPS);

    __half2 h0 = __floats2half2_rn(v.x * invx, v.y * invx);
    __half2 h1 = __floats2half2_rn(v.z * invx, v.w * invx);
    *(__half2*)(g_xh + gw * DIM + lane * 4)     = h0;
    *(__half2*)(g_xh + gw * DIM + lane * 4 + 2) = h1;

    if (lane == 0) {
        float T = tp[0], M = mp[0];
        float cosv = dot * invx * invp;
        g_p[gw]   = ex2f((cosv - M) * (1.4426950408889634f / T));
        g_num[gw] = 0.0f;
        g_den[gw] = 0.0f;
    }
}

// ---------------- kernel 2: pack mask bits per class ----------------
__global__ void k_pack(const float* __restrict__ nm) {
    __shared__ float s[32][33];
    int c0 = blockIdx.x * 32;
    int j0 = blockIdx.y * 32;
    int tx = threadIdx.x, ty = threadIdx.y;
    int c = c0 + tx;
    s[ty][tx] = (c < NCLS) ? nm[(j0 + ty) * NCLS + c] : 0.0f;
    __syncthreads();
    float v = s[tx][ty];
    unsigned word = __ballot_sync(0xffffffffu, v > 0.5f);
    int cc = c0 + ty;
    if (tx == 0 && cc < NCLS)
        g_maskbits[cc * (N_ROWS / 32) + (j0 >> 5)] = word;
}

// ---------------- kernel 3: fp16 mma.sync fused GEMM + exp + masked sums ----------------
__device__ __forceinline__ void prefetch_tile(uint32_t dstbase, int row0, int tid) {
    // 2048 16B chunks (128 rows x 16 chunks), 8 per thread at 256 threads
    #pragma unroll
    for (int it = 0; it < 8; ++it) {
        int c = tid + it * 256;
        int row = c >> 4, ch = c & 15;
        const void* src = (const void*)(g_xh + (row0 + row) * DIM + ch * 8);
        cp16(dstbase + toff(row, ch), src);
    }
}

__global__ void __launch_bounds__(256, 2)
k_main(const int* __restrict__ labels,
       const float* __restrict__ tp,
       const float* __restrict__ mp) {
    extern __shared__ char smem[];
    const uint32_t sb = smem_u32(smem);
    const int tid  = threadIdx.x;
    const int lane = tid & 31;
    const int wid  = tid >> 5;
    const int wm = wid >> 2;     // 0..1 : i block of 64
    const int wn = wid & 3;      // 0..3 : j block of 32
    const int i0 = blockIdx.x * TM;
    const int jbase = blockIdx.y * (N_ROWS / JSPLIT);

    const float T = tp[0], M = mp[0];
    const float scale = 1.4426950408889634f / T;
    const float nbias = -M * scale;

    // ldmatrix lane addressing
    const int arow_l = lane & 15;          // A: row within 16-row group
    const int akc    = lane >> 4;          // A: k-chunk select
    const int bnt_h  = (lane >> 4) & 1;    // B: nt within pair
    const int bkc    = (lane >> 3) & 1;    // B: k-chunk select
    const int brow_l = lane & 7;

    // my 8 rows (mt 0..3 x half 0..1)
    int   li8[8];
    float dacc[8], nacc[8];
    #pragma unroll
    for (int r = 0; r < 8; ++r) {
        int ig = i0 + wm * 64 + (r >> 1) * 16 + (lane >> 2) + (r & 1) * 8;
        li8[r] = labels[ig];
        dacc[r] = 0.0f; nacc[r] = 0.0f;
    }

    prefetch_tile(sb, i0, tid);                          // A resident
    prefetch_tile(sb + OFF_B, jbase, tid);               // B buf 0
    CP_COMMIT();
    prefetch_tile(sb + OFF_B + 32768, jbase + TN, tid);  // B buf 1
    CP_COMMIT();

    for (int t = 0; t < NT_TILES; ++t) {
        if (t >= NT_TILES - 2) { CP_WAIT(0); } else { CP_WAIT(1); }
        __syncthreads();

        const int j0 = jbase + t * TN;
        const uint32_t B = sb + OFF_B + (uint32_t)((t & 1) * 32768);
        const uint32_t A = sb;

        float acc[4][4][4];
        #pragma unroll
        for (int a = 0; a < 4; ++a)
            #pragma unroll
            for (int b = 0; b < 4; ++b)
                #pragma unroll
                for (int c = 0; c < 4; ++c) acc[a][b][c] = 0.0f;

        #pragma unroll
        for (int kk = 0; kk < 8; ++kk) {
            uint32_t ah[4][4], bh[4][2];
            #pragma unroll
            for (int mt = 0; mt < 4; ++mt) {
                int row = wm * 64 + mt * 16 + arow_l;
                uint32_t off = toff(row, kk * 2 + akc);
                LDSM_X4(ah[mt][0], ah[mt][1], ah[mt][2], ah[mt][3], A + off);
            }
            #pragma unroll
            for (int ntp = 0; ntp < 2; ++ntp) {
                int row = wn * 32 + (ntp * 2 + bnt_h) * 8 + brow_l;
                uint32_t off = toff(row, kk * 2 + bkc);
                LDSM_X4(bh[ntp * 2][0], bh[ntp * 2][1],
                        bh[ntp * 2 + 1][0], bh[ntp * 2 + 1][1], B + off);
            }
            #pragma unroll
            for (int mt = 0; mt < 4; ++mt)
                #pragma unroll
                for (int nt = 0; nt < 4; ++nt)
                    mma16816(acc[mt][nt], ah[mt], bh[nt]);
        }

        __syncthreads();
        if (t + 2 < NT_TILES) {
            prefetch_tile(sb + OFF_B + (uint32_t)((t & 1) * 32768), jbase + (t + 2) * TN, tid);
            CP_COMMIT();
        }

        // epilogue on register accumulators
        const int wword = (j0 >> 5) + wn;
        #pragma unroll
        for (int mt = 0; mt < 4; ++mt) {
            #pragma unroll
            for (int h = 0; h < 2; ++h) {
                const int r = mt * 2 + h;
                const unsigned w = g_maskbits[li8[r] * (N_ROWS / 32) + wword];
                const int ig = i0 + wm * 64 + mt * 16 + (lane >> 2) + h * 8;
                float de = 0.0f, nu = 0.0f;
                #pragma unroll
                for (int nt = 0; nt < 4; ++nt) {
                    #pragma unroll
                    for (int e = 0; e < 2; ++e) {
                        int col = wn * 32 + nt * 8 + (lane & 3) * 2 + e;
                        float ex = ex2f(fmaf(acc[mt][nt][h * 2 + e], scale, nbias));
                        ex = (j0 + col == ig) ? 0.0f : ex;
                        de += ex;
                        nu += ((w >> (col & 31)) & 1u) ? ex : 0.0f;
                    }
                }
                dacc[r] += de;
                nacc[r] += nu;
            }
        }
    }

    // quad reduce (lanes sharing the same row) and atomics
    #pragma unroll
    for (int r = 0; r < 8; ++r) {
        #pragma unroll
        for (int m = 1; m <= 2; m <<= 1) {
            dacc[r] += __shfl_xor_sync(0xffffffffu, dacc[r], m);
            nacc[r] += __shfl_xor_sync(0xffffffffu, nacc[r], m);
        }
    }
    if ((lane & 3) == 0) {
        #pragma unroll
        for (int r = 0; r < 8; ++r) {
            int ig = i0 + wm * 64 + (r >> 1) * 16 + (lane >> 2) + (r & 1) * 8;
            atomicAdd(&g_den[ig], dacc[r]);
            atomicAdd(&g_num[ig], nacc[r]);
        }
    }
}

// ---------------- kernel 4: final loss reduction (8 blocks, atomic) ----------------
__global__ void k_final(float* __restrict__ out, const float* __restrict__ tp) {
    __shared__ float s[1024];
    float T = tp[0];
    float sum = 0.0f;
    int base = blockIdx.x * 1024;
    for (int r = base + threadIdx.x; r < N_ROWS; r += 8192) {
        float p = g_p[r];
        sum += -__logf(T * (p + g_num[r]) / (p + g_den[r]));
    }
    s[threadIdx.x] = sum;
    __syncthreads();
    #pragma unroll
    for (int o = 512; o >= 32; o >>= 1) {
        if (threadIdx.x < o) s[threadIdx.x] += s[threadIdx.x + o];
        __syncthreads();
    }
    if (threadIdx.x < 32) {
        float v = s[threadIdx.x];
        #pragma unroll
        for (int m = 16; m; m >>= 1) v += __shfl_xor_sync(0xffffffffu, v, m);
        if (threadIdx.x == 0) atomicAdd(out, v / (float)N_ROWS);
    }
}

// ---------------- launch ----------------
extern "C" void kernel_launch(void* const* d_in, const int* in_sizes, int n_in,
                              void* d_out, int out_size) {
    const float* inst  = (const float*)d_in[0];
    const float* proxy = (const float*)d_in[1];
    const float* nmask = (const float*)d_in[2];
    const int*   lab   = (const int*)d_in[3];
    const float* temp  = (const float*)d_in[4];
    const float* marg  = (const float*)d_in[5];
    float* out = (float*)d_out;

    cudaFuncSetAttribute(k_main, cudaFuncAttributeMaxDynamicSharedMemorySize, SMEM_TOTAL);

    cudaMemsetAsync(out, 0, sizeof(float));
    k_normalize<<<(N_ROWS * 32) / 256, 256>>>(inst, proxy, temp, marg);
    k_pack<<<dim3((NCLS + 31) / 32, N_ROWS / 32), dim3(32, 32)>>>(nmask);
    k_main<<<dim3(N_ROWS / TM, JSPLIT), 256, SMEM_TOTAL>>>(lab, temp, marg);
    k_final<<<8, 1024>>>(out, temp);
}

// round 6
// speedup vs baseline: 6.1886x; 1.0928x over previous
#include <cuda_runtime.h>
#include <cuda_fp16.h>
#include <math.h>
#include <cstdint>

#define N_ROWS 8192
#define DIM    128
#define NCLS   1000
#define EPS    1e-8f
#define NTILE  64                    // 8192 / 128
#define NPAIRS (NTILE * (NTILE + 1) / 2)   // 2080

// ---------------- device scratch ----------------
__device__ __align__(16) __half g_xh[N_ROWS * DIM];          // fp16 normalized, 2 MB
__device__ float    g_p[N_ROWS];
__device__ float    g_num[N_ROWS];
__device__ float    g_den[N_ROWS];
__device__ unsigned g_maskbits[NCLS * (N_ROWS / 32)];        // [class][jword]

// ---------------- helpers ----------------
__device__ __forceinline__ float ex2f(float x) {
    float y; asm("ex2.approx.ftz.f32 %0, %1;" : "=f"(y) : "f"(x)); return y;
}
__device__ __forceinline__ uint32_t smem_u32(const void* p) {
    uint32_t a;
    asm("{ .reg .u64 t; cvta.to.shared.u64 t, %1; cvt.u32.u64 %0, t; }" : "=r"(a) : "l"(p));
    return a;
}
__device__ __forceinline__ void cp16(uint32_t dst, const void* src) {
    asm volatile("cp.async.cg.shared.global [%0], [%1], 16;" :: "r"(dst), "l"(src));
}
#define CP_COMMIT() asm volatile("cp.async.commit_group;" ::: "memory")
#define CP_WAIT(n)  asm volatile("cp.async.wait_group %0;" :: "n"(n) : "memory")

#define LDSM_X4(r0,r1,r2,r3,a) \
    asm volatile("ldmatrix.sync.aligned.m8n8.x4.shared.b16 {%0,%1,%2,%3}, [%4];" \
        : "=r"(r0),"=r"(r1),"=r"(r2),"=r"(r3) : "r"(a))

__device__ __forceinline__ void mma16816(float* d, const uint32_t* a, const uint32_t* b) {
    asm volatile("mma.sync.aligned.m16n8k16.row.col.f32.f16.f16.f32 "
        "{%0,%1,%2,%3}, {%4,%5,%6,%7}, {%8,%9}, {%0,%1,%2,%3};"
        : "+f"(d[0]), "+f"(d[1]), "+f"(d[2]), "+f"(d[3])
        : "r"(a[0]), "r"(a[1]), "r"(a[2]), "r"(a[3]), "r"(b[0]), "r"(b[1]));
}

// smem tile layout: 128 rows x 256B, 16B chunks XOR-swizzled by row
__device__ __forceinline__ uint32_t toff(int row, int ch) {
    return (uint32_t)(row * 256 + ((ch ^ (row & 7)) << 4));
}

#define OFF_B   32768
#define SMEM_TOTAL 65536   // A tile + B tile

// ---------------- kernel 1: normalize + fp16 cast + proxy term ----------------
__global__ void k_normalize(const float* __restrict__ x,
                            const float* __restrict__ proxy,
                            const float* __restrict__ tp,
                            const float* __restrict__ mp) {
    int gw   = (blockIdx.x * blockDim.x + threadIdx.x) >> 5;
    int lane = threadIdx.x & 31;
    if (gw >= N_ROWS) return;

    const float4 v  = *(const float4*)(x + gw * DIM + lane * 4);
    float ssx = v.x * v.x + v.y * v.y + v.z * v.z + v.w * v.w;
    const float4 pv = *(const float4*)(proxy + gw * DIM + lane * 4);
    float ssp = pv.x * pv.x + pv.y * pv.y + pv.z * pv.z + pv.w * pv.w;
    float dot = v.x * pv.x + v.y * pv.y + v.z * pv.z + v.w * pv.w;

    #pragma unroll
    for (int o = 16; o; o >>= 1) {
        ssx += __shfl_xor_sync(0xffffffffu, ssx, o);
        ssp += __shfl_xor_sync(0xffffffffu, ssp, o);
        dot += __shfl_xor_sync(0xffffffffu, dot, o);
    }
    float invx = 1.0f / fmaxf(sqrtf(ssx), EPS);
    float invp = 1.0f / fmaxf(sqrtf(ssp), EPS);

    __half2 h0 = __floats2half2_rn(v.x * invx, v.y * invx);
    __half2 h1 = __floats2half2_rn(v.z * invx, v.w * invx);
    *(__half2*)(g_xh + gw * DIM + lane * 4)     = h0;
    *(__half2*)(g_xh + gw * DIM + lane * 4 + 2) = h1;

    if (lane == 0) {
        float T = tp[0], M = mp[0];
        float cosv = dot * invx * invp;
        g_p[gw]   = ex2f((cosv - M) * (1.4426950408889634f / T));
        g_num[gw] = 0.0f;
        g_den[gw] = 0.0f;
    }
}

// ---------------- kernel 2: pack mask bits per class ----------------
__global__ void k_pack(const float* __restrict__ nm) {
    __shared__ float s[32][33];
    int c0 = blockIdx.x * 32;
    int j0 = blockIdx.y * 32;
    int tx = threadIdx.x, ty = threadIdx.y;
    int c = c0 + tx;
    s[ty][tx] = (c < NCLS) ? nm[(j0 + ty) * NCLS + c] : 0.0f;
    __syncthreads();
    float v = s[tx][ty];
    unsigned word = __ballot_sync(0xffffffffu, v > 0.5f);
    int cc = c0 + ty;
    if (tx == 0 && cc < NCLS)
        g_maskbits[cc * (N_ROWS / 32) + (j0 >> 5)] = word;
}

// ---------------- kernel 3: triangular fused GEMM + exp + dual-side sums ----------------
__global__ void __launch_bounds__(256, 2)
k_main(const int* __restrict__ labels,
       const float* __restrict__ tp,
       const float* __restrict__ mp) {
    extern __shared__ char smem[];
    const uint32_t sb = smem_u32(smem);
    const int tid  = threadIdx.x;
    const int lane = tid & 31;
    const int wid  = tid >> 5;
    const int wm = wid >> 2;     // 0..1 : i block of 64
    const int wn = wid & 3;      // 0..3 : j block of 32

    // ---- triangular decode: blockIdx.x -> (bi, bj), bi <= bj ----
    const int z = blockIdx.x;
    int bi = (int)(64.5f - sqrtf(64.5f * 64.5f - 2.0f * (float)z));
    while (bi * (129 - bi) / 2 > z) --bi;
    while ((bi + 1) * (128 - bi) / 2 <= z) ++bi;
    const int bj = bi + (z - bi * (129 - bi) / 2);
    const int i0 = bi * 128, j0 = bj * 128;
    const bool offdiag = (bi != bj);

    const float T = tp[0], M = mp[0];
    const float scale = 1.4426950408889634f / T;
    const float nbias = -M * scale;

    // ---- prefetch A (rows i0..) and B (rows j0..) ----
    #pragma unroll
    for (int it = 0; it < 8; ++it) {
        int c = tid + it * 256;
        int row = c >> 4, ch = c & 15;
        cp16(sb + toff(row, ch),        (const void*)(g_xh + (i0 + row) * DIM + ch * 8));
        cp16(sb + OFF_B + toff(row, ch),(const void*)(g_xh + (j0 + row) * DIM + ch * 8));
    }
    CP_COMMIT();

    // ldmatrix lane addressing
    const int arow_l = lane & 15;
    const int akc    = lane >> 4;
    const int bnt_h  = (lane >> 4) & 1;
    const int bkc    = (lane >> 3) & 1;
    const int brow_l = lane & 7;

    // row labels (8 owned rows) while cp.async is in flight
    int li8[8];
    #pragma unroll
    for (int r = 0; r < 8; ++r) {
        int ig = i0 + wm * 64 + (r >> 1) * 16 + (r & 1) * 8 + (lane >> 2);
        li8[r] = labels[ig];
    }
    // column labels (8 owned columns)
    int lc8[8];
    #pragma unroll
    for (int nt = 0; nt < 4; ++nt)
        #pragma unroll
        for (int e = 0; e < 2; ++e)
            lc8[nt * 2 + e] = labels[j0 + wn * 32 + nt * 8 + (lane & 3) * 2 + e];

    CP_WAIT(0);
    __syncthreads();

    // ---- MMA: 128x128 tile, warp tile 64x32 ----
    float acc[4][4][4];
    #pragma unroll
    for (int a = 0; a < 4; ++a)
        #pragma unroll
        for (int b = 0; b < 4; ++b)
            #pragma unroll
            for (int c = 0; c < 4; ++c) acc[a][b][c] = 0.0f;

    #pragma unroll
    for (int kk = 0; kk < 8; ++kk) {
        uint32_t ah[4][4], bh[4][2];
        #pragma unroll
        for (int mt = 0; mt < 4; ++mt) {
            int row = wm * 64 + mt * 16 + arow_l;
            LDSM_X4(ah[mt][0], ah[mt][1], ah[mt][2], ah[mt][3], sb + toff(row, kk * 2 + akc));
        }
        #pragma unroll
        for (int ntp = 0; ntp < 2; ++ntp) {
            int row = wn * 32 + (ntp * 2 + bnt_h) * 8 + brow_l;
            LDSM_X4(bh[ntp * 2][0], bh[ntp * 2][1],
                    bh[ntp * 2 + 1][0], bh[ntp * 2 + 1][1],
                    sb + OFF_B + toff(row, kk * 2 + bkc));
        }
        #pragma unroll
        for (int mt = 0; mt < 4; ++mt)
            #pragma unroll
            for (int nt = 0; nt < 4; ++nt)
                mma16816(acc[mt][nt], ah[mt], bh[nt]);
    }

    // ---- convert acc -> exp in place, with diag zeroing ----
    #pragma unroll
    for (int mt = 0; mt < 4; ++mt)
        #pragma unroll
        for (int h = 0; h < 2; ++h) {
            const int ig = i0 + wm * 64 + mt * 16 + h * 8 + (lane >> 2);
            #pragma unroll
            for (int nt = 0; nt < 4; ++nt)
                #pragma unroll
                for (int e = 0; e < 2; ++e) {
                    const int jg = j0 + wn * 32 + nt * 8 + (lane & 3) * 2 + e;
                    float ex = ex2f(fmaf(acc[mt][nt][h * 2 + e], scale, nbias));
                    acc[mt][nt][h * 2 + e] = (ig == jg) ? 0.0f : ex;
                }
        }

    // ---- row side: den_i / num_i (mask bit = column j of maskbits[label_i]) ----
    const int wword_row = (j0 >> 5) + wn;
    #pragma unroll
    for (int mt = 0; mt < 4; ++mt) {
        #pragma unroll
        for (int h = 0; h < 2; ++h) {
            const int r = mt * 2 + h;
            const unsigned w = g_maskbits[li8[r] * (N_ROWS / 32) + wword_row];
            float de = 0.0f, nu = 0.0f;
            #pragma unroll
            for (int nt = 0; nt < 4; ++nt)
                #pragma unroll
                for (int e = 0; e < 2; ++e) {
                    int col = wn * 32 + nt * 8 + (lane & 3) * 2 + e;
                    float ex = acc[mt][nt][h * 2 + e];
                    de += ex;
                    nu += ((w >> (col & 31)) & 1u) ? ex : 0.0f;
                }
            // quad reduce over the 4 lanes sharing this row
            #pragma unroll
            for (int m = 1; m <= 2; m <<= 1) {
                de += __shfl_xor_sync(0xffffffffu, de, m);
                nu += __shfl_xor_sync(0xffffffffu, nu, m);
            }
            if ((lane & 3) == 0) {
                int ig = i0 + wm * 64 + mt * 16 + h * 8 + (lane >> 2);
                atomicAdd(&g_den[ig], de);
                atomicAdd(&g_num[ig], nu);
            }
        }
    }

    // ---- column side (off-diagonal only): den_j / num_j (mask bit = row i of maskbits[label_j]) ----
    if (offdiag) {
        #pragma unroll
        for (int nt = 0; nt < 4; ++nt) {
            #pragma unroll
            for (int e = 0; e < 2; ++e) {
                const int lc = lc8[nt * 2 + e];
                const unsigned cw0 = g_maskbits[lc * (N_ROWS / 32) + (i0 >> 5) + wm * 2];
                const unsigned cw1 = g_maskbits[lc * (N_ROWS / 32) + (i0 >> 5) + wm * 2 + 1];
                float cd = 0.0f, cn = 0.0f;
                #pragma unroll
                for (int mt = 0; mt < 4; ++mt)
                    #pragma unroll
                    for (int h = 0; h < 2; ++h) {
                        float ex = acc[mt][nt][h * 2 + e];
                        const unsigned w = (mt >= 2) ? cw1 : cw0;
                        const int bit = (mt * 16 + h * 8 + (lane >> 2)) & 31;
                        cd += ex;
                        cn += ((w >> bit) & 1u) ? ex : 0.0f;
                    }
                // reduce over the 8 lanes sharing this column (lane>>2 varies)
                #pragma unroll
                for (int m = 4; m <= 16; m <<= 1) {
                    cd += __shfl_xor_sync(0xffffffffu, cd, m);
                    cn += __shfl_xor_sync(0xffffffffu, cn, m);
                }
                if ((lane >> 2) == 0) {
                    int jg = j0 + wn * 32 + nt * 8 + (lane & 3) * 2 + e;
                    atomicAdd(&g_den[jg], cd);
                    atomicAdd(&g_num[jg], cn);
                }
            }
        }
    }
}

// ---------------- kernel 4: final loss reduction (8 blocks, atomic) ----------------
__global__ void k_final(float* __restrict__ out, const float* __restrict__ tp) {
    __shared__ float s[1024];
    float T = tp[0];
    float sum = 0.0f;
    int base = blockIdx.x * 1024;
    for (int r = base + threadIdx.x; r < N_ROWS; r += 8192) {
        float p = g_p[r];
        sum += -__logf(T * (p + g_num[r]) / (p + g_den[r]));
    }
    s[threadIdx.x] = sum;
    __syncthreads();
    #pragma unroll
    for (int o = 512; o >= 32; o >>= 1) {
        if (threadIdx.x < o) s[threadIdx.x] += s[threadIdx.x + o];
        __syncthreads();
    }
    if (threadIdx.x < 32) {
        float v = s[threadIdx.x];
        #pragma unroll
        for (int m = 16; m; m >>= 1) v += __shfl_xor_sync(0xffffffffu, v, m);
        if (threadIdx.x == 0) atomicAdd(out, v / (float)N_ROWS);
    }
}

// ---------------- launch ----------------
extern "C" void kernel_launch(void* const* d_in, const int* in_sizes, int n_in,
                              void* d_out, int out_size) {
    const float* inst  = (const float*)d_in[0];
    const float* proxy = (const float*)d_in[1];
    const float* nmask = (const float*)d_in[2];
    const int*   lab   = (const int*)d_in[3];
    const float* temp  = (const float*)d_in[4];
    const float* marg  = (const float*)d_in[5];
    float* out = (float*)d_out;

    cudaFuncSetAttribute(k_main, cudaFuncAttributeMaxDynamicSharedMemorySize, SMEM_TOTAL);

    cudaMemsetAsync(out, 0, sizeof(float));
    k_normalize<<<(N_ROWS * 32) / 256, 256>>>(inst, proxy, temp, marg);
    k_pack<<<dim3((NCLS + 31) / 32, N_ROWS / 32), dim3(32, 32)>>>(nmask);
    k_main<<<NPAIRS, 256, SMEM_TOTAL>>>(lab, temp, marg);
    k_final<<<8, 1024>>>(out, temp);
}